// round 12
// baseline (speedup 1.0000x reference)
#include <cuda_runtime.h>
#include <cuda_fp16.h>
#include <mma.h>

using namespace nvcuda;

// ---------------------------------------------------------------------------
// HybridGNN: 2x GCNConv(+ReLU+BN) -> global mean pool -> concat rdkit ->
//            MLP (Linear+ReLU+BN) x2 -> Linear -> [G]
// Rows prescaled by their own dinv =>
//   agg[n] = dn*(src'[n] + sum src'[r]); wsum[n] = dn*(dn + sum dinv[r])
// Gather inner loops use explicit batch-of-8 prefetch for MLP=8.
// ---------------------------------------------------------------------------

namespace {
constexpr int F_DIM = 64;
constexpr int H1    = 128;
constexpr int HH    = 256;   // 2H
constexpr int RDK   = 200;
constexpr int ZD    = 456;   // 2H + R
constexpr int NMAX  = 100000;
constexpr int GMAX  = 4096;
constexpr int SLOTS = 96;
constexpr int OFCAP = 4096;
constexpr int STATS_TOTAL = 1536;
constexpr float EPS = 1e-5f;
}

__device__ float  g_dinv[NMAX];
__device__ float  g_wsum[NMAX];
__device__ int    g_degc[NMAX];
__device__ int    g_csr [(size_t)NMAX * SLOTS];
__device__ int    g_ovf [OFCAP];
__device__ int    g_ovfcnt;
__device__ __half g_x16 [(size_t)NMAX * F_DIM];   // prescaled: dinv[n]*x[n]
__device__ __half g_h16 [(size_t)NMAX * H1];      // prescaled: dinv[n]*h1[n]
__device__ __half g_agg16[(size_t)NMAX * H1];
__device__ __half g_w1h[F_DIM * H1];
__device__ __half g_w2h[H1 * HH];
__device__ float  g_stats[STATS_TOTAL];
__device__ float  g_pool[(size_t)GMAX * HH];
__device__ float  g_cnt [GMAX];
__device__ float  g_z   [(size_t)GMAX * ZD];
__device__ float  g_z1  [(size_t)GMAX * HH];
__device__ float  g_z2  [(size_t)GMAX * H1];

__device__ __forceinline__ void red4(float* p, float4 v) {
    asm volatile("red.global.add.v4.f32 [%0], {%1,%2,%3,%4};"
                 :: "l"(p), "f"(v.x), "f"(v.y), "f"(v.z), "f"(v.w)
                 : "memory");
}

__device__ __forceinline__ void f2h4(const float* in, __half* out, size_t i4) {
    float4 v = ((const float4*)in)[i4];
    __half2 a = __floats2half2_rn(v.x, v.y);
    __half2 b = __floats2half2_rn(v.z, v.w);
    uint2 packed;
    packed.x = *(unsigned int*)&a;
    packed.y = *(unsigned int*)&b;
    ((uint2*)out)[i4] = packed;
}

// ---------------------------------------------------------------------------
// Setup: zero degc/ovfcnt/stats/pool/cnt + fp16-convert W1, W2
// ---------------------------------------------------------------------------
__global__ void k_setup(int* degc, int* ovfcnt, float* stats, float* pool, float* cnt,
                        const float* W1, __half* w1h,
                        const float* W2, __half* w2h, int N, int G) {
    long long i = (long long)blockIdx.x * blockDim.x + threadIdx.x;
    long long o0 = N;
    long long o1 = o0 + 1;
    long long o2 = o1 + STATS_TOTAL;
    long long o3 = o2 + (long long)G * HH;
    long long o4 = o3 + G;
    long long o5 = o4 + F_DIM * H1 / 4;
    long long o6 = o5 + H1 * HH / 4;
    if (i < o0)      degc[i] = 0;
    else if (i < o1) *ovfcnt = 0;
    else if (i < o2) stats[i - o1] = 0.0f;
    else if (i < o3) pool[i - o2] = 0.0f;
    else if (i < o4) cnt[i - o3] = 0.0f;
    else if (i < o5) f2h4(W1, w1h, i - o4);
    else if (i < o6) f2h4(W2, w2h, i - o5);
}

// ---------------------------------------------------------------------------
// CSR build
// ---------------------------------------------------------------------------
__global__ void k_csr_build(const int* __restrict__ row, const int* __restrict__ col,
                            int* __restrict__ cursor, int* __restrict__ csr,
                            int* __restrict__ ovf, int* __restrict__ ovfcnt, int E) {
    int e = blockIdx.x * blockDim.x + threadIdx.x;
    if (e >= E) return;
    int c = col[e];
    int slot = atomicAdd(&cursor[c], 1);
    if (slot < SLOTS) {
        csr[(size_t)c * SLOTS + slot] = row[e];
    } else {
        int o = atomicAdd(ovfcnt, 1);
        if (o < OFCAP) ovf[o] = e;
    }
}

// dinv + per-graph counts + prescale x -> fp16
__global__ void k_dinv_prescale(const int* __restrict__ deg, float* __restrict__ dinv,
                                const int* __restrict__ batch, float* __restrict__ cnt,
                                const float* __restrict__ x, __half* __restrict__ x16,
                                int N) {
    long long t = (long long)blockIdx.x * blockDim.x + threadIdx.x;
    if (t >= (long long)N * (F_DIM / 4)) return;
    int n  = (int)(t >> 4);
    int f4 = (int)(t & 15);
    float dv = rsqrtf((float)deg[n] + 1.0f);
    if (f4 == 0) {
        dinv[n] = dv;
        atomicAdd(&cnt[batch[n]], 1.0f);
    }
    float4 v = ((const float4*)x)[t];
    __half2 a = __floats2half2_rn(v.x * dv, v.y * dv);
    __half2 b = __floats2half2_rn(v.z * dv, v.w * dv);
    uint2 packed;
    packed.x = *(unsigned int*)&a;
    packed.y = *(unsigned int*)&b;
    ((uint2*)x16)[t] = packed;
}

// ---------------------------------------------------------------------------
// Gather (warp per node), prescaled fp16 src, batch-of-8 prefetch (MLP=8).
//   M==64 (layer 1, !AFFINE): out = dn*acc; wsum[n] computed in a pre-loop.
//   M==128 (layer 2, AFFINE): out = a(.)(dn*acc) + wsum[n]*b
// ---------------------------------------------------------------------------
template <int M, bool AFFINE>
__global__ void k_gather_h(const int* __restrict__ csr, const int* __restrict__ deg,
                           const float* __restrict__ dinv, const __half* __restrict__ src,
                           const float* __restrict__ stats,
                           const float* __restrict__ gamma, const float* __restrict__ beta,
                           float invN, float* __restrict__ wsum_buf,
                           __half* __restrict__ out, int N) {
    __shared__ float sca[AFFINE ? M : 1];
    __shared__ float scb[AFFINE ? M : 1];
    if constexpr (AFFINE) {
        for (int f = threadIdx.x; f < M; f += blockDim.x) {
            float mu = stats[f] * invN;
            float var = stats[M + f] * invN - mu * mu;
            float a = gamma[f] * rsqrtf(var + EPS);
            sca[f] = a;
            scb[f] = beta[f] - a * mu;
        }
        __syncthreads();
    }

    int warp = (blockIdx.x * blockDim.x + threadIdx.x) >> 5;
    int lane = threadIdx.x & 31;
    if (warp >= N) return;
    const int n = warp;
    int d = deg[n];
    if (d > SLOTS) d = SLOTS;
    const float dn = dinv[n];
    const int* list = csr + (size_t)n * SLOTS;

    if constexpr (M == 128) {
        const float w = wsum_buf[n];
        uint2 raw = ((const uint2*)(src + (size_t)n * M))[lane];
        float2 f0 = __half22float2(*(__half2*)&raw.x);
        float2 f1 = __half22float2(*(__half2*)&raw.y);
        float4 acc = make_float4(f0.x, f0.y, f1.x, f1.y);
        for (int base = 0; base < d; base += 32) {
            int li = base + lane;
            int idx = (li < d) ? list[li] : 0;
            int m = min(32, d - base);
            int mfull = m & ~7;
            for (int j0 = 0; j0 < mfull; j0 += 8) {
                int rr[8];
                uint2 v[8];
#pragma unroll
                for (int j = 0; j < 8; j++)
                    rr[j] = __shfl_sync(0xffffffffu, idx, j0 + j);
#pragma unroll
                for (int j = 0; j < 8; j++)
                    v[j] = ((const uint2*)(src + (size_t)rr[j] * M))[lane];
#pragma unroll
                for (int j = 0; j < 8; j++) {
                    float2 a0 = __half22float2(*(__half2*)&v[j].x);
                    float2 a1 = __half22float2(*(__half2*)&v[j].y);
                    acc.x += a0.x; acc.y += a0.y; acc.z += a1.x; acc.w += a1.y;
                }
            }
            for (int j = mfull; j < m; j++) {
                int r0 = __shfl_sync(0xffffffffu, idx, j);
                uint2 rv = ((const uint2*)(src + (size_t)r0 * M))[lane];
                float2 a0 = __half22float2(*(__half2*)&rv.x);
                float2 a1 = __half22float2(*(__half2*)&rv.y);
                acc.x += a0.x; acc.y += a0.y; acc.z += a1.x; acc.w += a1.y;
            }
        }
        acc.x *= dn; acc.y *= dn; acc.z *= dn; acc.w *= dn;
        float4 a4 = ((const float4*)sca)[lane];
        float4 b4 = ((const float4*)scb)[lane];
        acc.x = a4.x * acc.x + w * b4.x;
        acc.y = a4.y * acc.y + w * b4.y;
        acc.z = a4.z * acc.z + w * b4.z;
        acc.w = a4.w * acc.w + w * b4.w;
        __half2 o0 = __floats2half2_rn(acc.x, acc.y);
        __half2 o1 = __floats2half2_rn(acc.z, acc.w);
        uint2 packed;
        packed.x = *(unsigned int*)&o0;
        packed.y = *(unsigned int*)&o1;
        ((uint2*)(out + (size_t)n * M))[lane] = packed;
    } else {  // M == 64, layer 1: wsum in a decoupled pre-loop
        float dsum = 0.0f;
        for (int li = lane; li < d; li += 32)
            dsum += dinv[list[li]];
#pragma unroll
        for (int off = 16; off > 0; off >>= 1)
            dsum += __shfl_xor_sync(0xffffffffu, dsum, off);
        if (lane == 0) wsum_buf[n] = dn * (dn + dsum);

        unsigned int raw = ((const unsigned int*)(src + (size_t)n * M))[lane];
        float2 f0 = __half22float2(*(__half2*)&raw);
        float2 acc = make_float2(f0.x, f0.y);
        for (int base = 0; base < d; base += 32) {
            int li = base + lane;
            int idx = (li < d) ? list[li] : 0;
            int m = min(32, d - base);
            int mfull = m & ~7;
            for (int j0 = 0; j0 < mfull; j0 += 8) {
                int rr[8];
                unsigned int v[8];
#pragma unroll
                for (int j = 0; j < 8; j++)
                    rr[j] = __shfl_sync(0xffffffffu, idx, j0 + j);
#pragma unroll
                for (int j = 0; j < 8; j++)
                    v[j] = ((const unsigned int*)(src + (size_t)rr[j] * M))[lane];
#pragma unroll
                for (int j = 0; j < 8; j++) {
                    float2 a0 = __half22float2(*(__half2*)&v[j]);
                    acc.x += a0.x; acc.y += a0.y;
                }
            }
            for (int j = mfull; j < m; j++) {
                int r0 = __shfl_sync(0xffffffffu, idx, j);
                unsigned int rv = ((const unsigned int*)(src + (size_t)r0 * M))[lane];
                float2 a0 = __half22float2(*(__half2*)&rv);
                acc.x += a0.x; acc.y += a0.y;
            }
        }
        acc.x *= dn; acc.y *= dn;
        __half2 o0 = __floats2half2_rn(acc.x, acc.y);
        ((unsigned int*)(out + (size_t)n * M))[lane] = *(unsigned int*)&o0;
    }
}

// Overflow fallback (expected count 0), prescaled algebra
template <int M, bool AFFINE>
__global__ void k_overflow_h(const int* __restrict__ row, const int* __restrict__ col,
                             const int* __restrict__ ovf, const int* __restrict__ ovfcnt,
                             const float* __restrict__ dinv,
                             const __half* __restrict__ src,
                             const float* __restrict__ stats,
                             const float* __restrict__ gamma, const float* __restrict__ beta,
                             float invN, __half* __restrict__ dst) {
    __shared__ float sca[AFFINE ? M : 1];
    __shared__ float scb[AFFINE ? M : 1];
    if constexpr (AFFINE) {
        for (int f = threadIdx.x; f < M; f += blockDim.x) {
            float mu = stats[f] * invN;
            float var = stats[M + f] * invN - mu * mu;
            float a = gamma[f] * rsqrtf(var + EPS);
            sca[f] = a;
            scb[f] = beta[f] - a * mu;
        }
        __syncthreads();
    }
    int cnt = *ovfcnt;
    if (cnt > OFCAP) cnt = OFCAP;
    for (int i = threadIdx.x; i < cnt * (M / 4); i += blockDim.x) {
        int e = ovf[i / (M / 4)];
        int l = i % (M / 4);
        int r = row[e], c = col[e];
        float dc = dinv[c];
        uint2 raw = ((const uint2*)(src + (size_t)r * M))[l];
        float2 f0 = __half22float2(*(__half2*)&raw.x);
        float2 f1 = __half22float2(*(__half2*)&raw.y);
        float4 v = make_float4(f0.x * dc, f0.y * dc, f1.x * dc, f1.y * dc);
        if constexpr (AFFINE) {
            float nrm = dc * dinv[r];
            float4 a4 = ((const float4*)sca)[l];
            float4 b4 = ((const float4*)scb)[l];
            v.x = a4.x * v.x + nrm * b4.x; v.y = a4.y * v.y + nrm * b4.y;
            v.z = a4.z * v.z + nrm * b4.z; v.w = a4.w * v.w + nrm * b4.w;
        }
        __half2* p = (__half2*)(dst + (size_t)c * M + l * 4);
        atomicAdd(p,     __floats2half2_rn(v.x, v.y));
        atomicAdd(p + 1, __floats2half2_rn(v.z, v.w));
    }
}

// ---------------------------------------------------------------------------
// fp16 HMMA GEMM: relu(A@B + bias), fused stats, optional POOL,
// STORE_MODE 0=none / 2=fp16 (row-scaled by rowscale[] if given).
// ---------------------------------------------------------------------------
template <bool POOL, int STORE_MODE>
__launch_bounds__(256)
__global__ void k_gemm_h(const __half* __restrict__ A, const __half* __restrict__ B,
                         const float* __restrict__ bias,
                         __half* __restrict__ C16, const float* __restrict__ rowscale,
                         const int* __restrict__ batch, float* __restrict__ pool,
                         float* __restrict__ stats,
                         int N, int K, int M) {
    constexpr int LDA = 32;
    constexpr int LDB = 144;
    __shared__ __half Ah[128 * LDA];
    __shared__ __half Bh[16 * LDB];
    __shared__ float  staging[64 * 128];

    const int tx   = threadIdx.x;
    const int warp = tx >> 5;
    const int wr   = warp >> 2;
    const int wc   = warp & 3;
    const int trow = tx >> 4;
    const int tcol = tx & 15;
    const int row0 = blockIdx.x * 128;
    const int colT = blockIdx.y * 128;
    const int c0   = colT + tcol * 8;

    wmma::fragment<wmma::accumulator, 16, 16, 16, float> acc[4][2];
#pragma unroll
    for (int m = 0; m < 4; m++)
#pragma unroll
        for (int n = 0; n < 2; n++) wmma::fill_fragment(acc[m][n], 0.0f);

    for (int k0 = 0; k0 < K; k0 += 16) {
        {
            int r  = tx >> 1;
            int h8 = (tx & 1) * 8;
            uint4 v = make_uint4(0, 0, 0, 0);
            int grow = row0 + r;
            if (grow < N) v = *(const uint4*)&A[(size_t)grow * K + k0 + h8];
            *(uint4*)&Ah[r * LDA + h8] = v;
        }
        {
            int kk = tx >> 4;
            int c8 = (tx & 15) * 8;
            uint4 v = *(const uint4*)&B[(size_t)(k0 + kk) * M + colT + c8];
            *(uint4*)&Bh[kk * LDB + c8] = v;
        }
        __syncthreads();

        wmma::fragment<wmma::matrix_b, 16, 16, 16, __half, wmma::row_major> bf[2];
#pragma unroll
        for (int n = 0; n < 2; n++)
            wmma::load_matrix_sync(bf[n], &Bh[wc * 32 + n * 16], LDB);
#pragma unroll
        for (int m = 0; m < 4; m++) {
            wmma::fragment<wmma::matrix_a, 16, 16, 16, __half, wmma::row_major> af;
            wmma::load_matrix_sync(af, &Ah[(wr * 64 + m * 16) * LDA], LDA);
#pragma unroll
            for (int n = 0; n < 2; n++)
                wmma::mma_sync(acc[m][n], af, bf[n], acc[m][n]);
        }
        __syncthreads();
    }

    float bv[8];
    *(float4*)&bv[0] = *(const float4*)&bias[c0];
    *(float4*)&bv[4] = *(const float4*)&bias[c0 + 4];

    float s_part[8], q_part[8];
#pragma unroll
    for (int c = 0; c < 8; c++) { s_part[c] = 0.f; q_part[c] = 0.f; }

#pragma unroll
    for (int half = 0; half < 2; half++) {
#pragma unroll
        for (int mi = 0; mi < 2; mi++)
#pragma unroll
            for (int n = 0; n < 2; n++)
                wmma::store_matrix_sync(&staging[(wr * 32 + mi * 16) * 128 + wc * 32 + n * 16],
                                        acc[2 * half + mi][n], 128, wmma::mem_row_major);
        __syncthreads();

#pragma unroll
        for (int k = 0; k < 4; k++) {
            int r_st = trow * 4 + k;
            int grow = row0 + (r_st >> 5) * 64 + (half * 2 + ((r_st >> 4) & 1)) * 16 + (r_st & 15);
            if (grow < N) {
                float v[8];
                *(float4*)&v[0] = *(float4*)&staging[r_st * 128 + tcol * 8];
                *(float4*)&v[4] = *(float4*)&staging[r_st * 128 + tcol * 8 + 4];
#pragma unroll
                for (int c = 0; c < 8; c++) {
                    v[c] = fmaxf(v[c] + bv[c], 0.0f);
                    s_part[c] += v[c];
                    q_part[c] += v[c] * v[c];
                }
                if constexpr (STORE_MODE == 2) {
                    float rs = rowscale ? rowscale[grow] : 1.0f;
                    __half hv[8];
#pragma unroll
                    for (int c = 0; c < 8; c++) hv[c] = __float2half_rn(v[c] * rs);
                    *(uint4*)&C16[(size_t)grow * M + c0] = *(uint4*)hv;
                }
                if constexpr (POOL) {
                    int g = batch[grow];
                    red4(pool + (size_t)g * M + c0,     *(float4*)&v[0]);
                    red4(pool + (size_t)g * M + c0 + 4, *(float4*)&v[4]);
                }
            }
        }
        __syncthreads();
    }

    float* Rsum = staging;
    float* Rsq  = staging + 16 * 128;
    *(float4*)&Rsum[trow * 128 + tcol * 8]     = *(float4*)&s_part[0];
    *(float4*)&Rsum[trow * 128 + tcol * 8 + 4] = *(float4*)&s_part[4];
    *(float4*)&Rsq [trow * 128 + tcol * 8]     = *(float4*)&q_part[0];
    *(float4*)&Rsq [trow * 128 + tcol * 8 + 4] = *(float4*)&q_part[4];
    __syncthreads();
#pragma unroll
    for (int st = 8; st >= 1; st >>= 1) {
        if (trow < st) {
#pragma unroll
            for (int c = 0; c < 8; c++) {
                Rsum[trow * 128 + tcol * 8 + c] += Rsum[(trow + st) * 128 + tcol * 8 + c];
                Rsq [trow * 128 + tcol * 8 + c] += Rsq [(trow + st) * 128 + tcol * 8 + c];
            }
        }
        __syncthreads();
    }
    if (trow == 0) {
#pragma unroll
        for (int c = 0; c < 8; c++) {
            atomicAdd(&stats[c0 + c],     Rsum[tcol * 8 + c]);
            atomicAdd(&stats[M + c0 + c], Rsq [tcol * 8 + c]);
        }
    }
}

// ---------------------------------------------------------------------------
// fp32 SGEMM (MLP head): stats fused, fp32 C
// ---------------------------------------------------------------------------
__launch_bounds__(256, 2)
__global__ void k_gemm128(const float* __restrict__ A, const float* __restrict__ B,
                          const float* __restrict__ bias, float* __restrict__ C,
                          float* __restrict__ stats,
                          int N, int K, int M) {
    constexpr int BM = 128, BN = 128, KT = 16;
    __shared__ float As[KT][BM];
    __shared__ float Bs[KT][BN];

    const int row0 = blockIdx.x * BM;
    const int colT = blockIdx.y * BN;
    const int tx   = threadIdx.x;
    const int tcol = tx & 15;
    const int trow = tx >> 4;
    const int c0   = colT + tcol * 8;
    const int r0   = row0 + trow * 8;

    float acc[8][8];
#pragma unroll
    for (int r = 0; r < 8; r++)
#pragma unroll
        for (int c = 0; c < 8; c++) acc[r][c] = 0.0f;

    for (int k0 = 0; k0 < K; k0 += KT) {
#pragma unroll
        for (int i = 0; i < 2; i++) {
            int idx = tx + i * 256;
            int kk  = idx >> 5;
            int cq  = idx & 31;
            int k   = k0 + kk;
            float4 v = make_float4(0.f, 0.f, 0.f, 0.f);
            if (k < K) v = *(const float4*)&B[(size_t)k * M + colT + cq * 4];
            *(float4*)&Bs[kk][cq * 4] = v;
        }
#pragma unroll
        for (int i = 0; i < 2; i++) {
            int idx = tx + i * 256;
            int r   = idx >> 2;
            int kq  = idx & 3;
            int row = row0 + r;
            int k   = k0 + kq * 4;
            float4 v = make_float4(0.f, 0.f, 0.f, 0.f);
            if (row < N) {
                if (k + 3 < K) {
                    v = *(const float4*)&A[(size_t)row * K + k];
                } else {
                    float t0 = (k + 0 < K) ? A[(size_t)row * K + k + 0] : 0.f;
                    float t1 = (k + 1 < K) ? A[(size_t)row * K + k + 1] : 0.f;
                    float t2 = (k + 2 < K) ? A[(size_t)row * K + k + 2] : 0.f;
                    float t3 = (k + 3 < K) ? A[(size_t)row * K + k + 3] : 0.f;
                    v = make_float4(t0, t1, t2, t3);
                }
            }
            As[kq * 4 + 0][r] = v.x;
            As[kq * 4 + 1][r] = v.y;
            As[kq * 4 + 2][r] = v.z;
            As[kq * 4 + 3][r] = v.w;
        }
        __syncthreads();

#pragma unroll
        for (int kk = 0; kk < KT; kk++) {
            float a[8], b[8];
            *(float4*)&a[0] = *(const float4*)&As[kk][trow * 8];
            *(float4*)&a[4] = *(const float4*)&As[kk][trow * 8 + 4];
            *(float4*)&b[0] = *(const float4*)&Bs[kk][tcol * 8];
            *(float4*)&b[4] = *(const float4*)&Bs[kk][tcol * 8 + 4];
#pragma unroll
            for (int r = 0; r < 8; r++)
#pragma unroll
                for (int c = 0; c < 8; c++)
                    acc[r][c] += a[r] * b[c];
        }
        __syncthreads();
    }

    float bv[8];
    *(float4*)&bv[0] = *(const float4*)&bias[c0];
    *(float4*)&bv[4] = *(const float4*)&bias[c0 + 4];

    float s_part[8], q_part[8];
#pragma unroll
    for (int c = 0; c < 8; c++) { s_part[c] = 0.f; q_part[c] = 0.f; }

#pragma unroll
    for (int r = 0; r < 8; r++) {
        int row = r0 + r;
        if (row < N) {
#pragma unroll
            for (int c = 0; c < 8; c++) {
                acc[r][c] = fmaxf(acc[r][c] + bv[c], 0.0f);
                s_part[c] += acc[r][c];
                q_part[c] += acc[r][c] * acc[r][c];
            }
            *(float4*)&C[(size_t)row * M + c0]     = *(float4*)&acc[r][0];
            *(float4*)&C[(size_t)row * M + c0 + 4] = *(float4*)&acc[r][4];
        }
    }

    *(float4*)&As[trow][tcol * 8]     = *(float4*)&s_part[0];
    *(float4*)&As[trow][tcol * 8 + 4] = *(float4*)&s_part[4];
    *(float4*)&Bs[trow][tcol * 8]     = *(float4*)&q_part[0];
    *(float4*)&Bs[trow][tcol * 8 + 4] = *(float4*)&q_part[4];
    __syncthreads();
#pragma unroll
    for (int st = 8; st >= 1; st >>= 1) {
        if (trow < st) {
#pragma unroll
            for (int c = 0; c < 8; c++) {
                As[trow][tcol * 8 + c] += As[trow + st][tcol * 8 + c];
                Bs[trow][tcol * 8 + c] += Bs[trow + st][tcol * 8 + c];
            }
        }
        __syncthreads();
    }
    if (trow == 0) {
#pragma unroll
        for (int c = 0; c < 8; c++) {
            atomicAdd(&stats[c0 + c],     As[0][tcol * 8 + c]);
            atomicAdd(&stats[M + c0 + c], Bs[0][tcol * 8 + c]);
        }
    }
}

// ---------------------------------------------------------------------------
// BN apply (mBN1 on z1)
// ---------------------------------------------------------------------------
template <int M>
__global__ void k_bn_apply(float* __restrict__ h, const float* __restrict__ stats,
                           const float* __restrict__ gamma, const float* __restrict__ beta,
                           int N) {
    size_t i = (size_t)blockIdx.x * blockDim.x + threadIdx.x;
    if (i >= (size_t)N * M) return;
    int f = (int)(i % M);
    float inv_n = 1.0f / (float)N;
    float mu = stats[f] * inv_n;
    float var = stats[M + f] * inv_n - mu * mu;
    float sc = gamma[f] * rsqrtf(var + EPS);
    h[i] = (h[i] - mu) * sc + beta[f];
}

// ---------------------------------------------------------------------------
// Concat: mean + BN2-apply (coef inline) + rdkit
// ---------------------------------------------------------------------------
__global__ void k_concat(const float* __restrict__ pool, const float* __restrict__ cnt,
                         const float* __restrict__ stats,
                         const float* __restrict__ gamma, const float* __restrict__ beta,
                         float invN,
                         const float* __restrict__ rdkit, float* __restrict__ z, int G) {
    int t = blockIdx.x * blockDim.x + threadIdx.x;
    if (t >= G * ZD) return;
    int g = t / ZD, f = t % ZD;
    float out;
    if (f < HH) {
        float mu = stats[f] * invN;
        float var = stats[HH + f] * invN - mu * mu;
        float a = gamma[f] * rsqrtf(var + EPS);
        float b = beta[f] - a * mu;
        float mean = pool[(size_t)g * HH + f] / fmaxf(cnt[g], 1.0f);
        out = a * mean + b;
    } else {
        out = rdkit[(size_t)g * RDK + (f - HH)];
    }
    z[t] = out;
}

// ---------------------------------------------------------------------------
// Final projection with mBN2-apply folded in
// ---------------------------------------------------------------------------
__global__ void k_final(const float* __restrict__ z2, const float* __restrict__ stats,
                        const float* __restrict__ gamma, const float* __restrict__ beta,
                        float invG,
                        const float* __restrict__ w, const float* __restrict__ b,
                        float* __restrict__ out, int G) {
    int warp = (blockIdx.x * blockDim.x + threadIdx.x) >> 5;
    int lane = threadIdx.x & 31;
    if (warp >= G) return;
    const float* zr = z2 + (size_t)warp * H1;
    float s = 0.0f;
#pragma unroll
    for (int q = 0; q < 4; q++) {
        int f = lane + q * 32;
        float mu = stats[f] * invG;
        float var = stats[H1 + f] * invG - mu * mu;
        float a = gamma[f] * rsqrtf(var + EPS);
        float bb = beta[f] - a * mu;
        s += w[f] * (a * zr[f] + bb);
    }
#pragma unroll
    for (int off = 16; off > 0; off >>= 1)
        s += __shfl_down_sync(0xffffffffu, s, off);
    if (lane == 0) out[warp] = s + b[0];
}

// ---------------------------------------------------------------------------
// Launch
// ---------------------------------------------------------------------------
extern "C" void kernel_launch(void* const* d_in, const int* in_sizes, int n_in,
                              void* d_out, int out_size) {
    const float* x      = (const float*)d_in[0];
    const int*   ei     = (const int*)d_in[1];
    const int*   batch  = (const int*)d_in[2];
    const float* rdkit  = (const float*)d_in[3];
    const float* W1  = (const float*)d_in[4];
    const float* b1  = (const float*)d_in[5];
    const float* gm1 = (const float*)d_in[6];
    const float* be1 = (const float*)d_in[7];
    const float* W2  = (const float*)d_in[8];
    const float* b2  = (const float*)d_in[9];
    const float* gm2 = (const float*)d_in[10];
    const float* be2 = (const float*)d_in[11];
    const float* mW1 = (const float*)d_in[12];
    const float* mb1 = (const float*)d_in[13];
    const float* mg1 = (const float*)d_in[14];
    const float* mbe1= (const float*)d_in[15];
    const float* mW2 = (const float*)d_in[16];
    const float* mb2 = (const float*)d_in[17];
    const float* mg2 = (const float*)d_in[18];
    const float* mbe2= (const float*)d_in[19];
    const float* mW3 = (const float*)d_in[20];
    const float* mb3 = (const float*)d_in[21];
    float* out = (float*)d_out;

    const int N = in_sizes[2];
    const int E = in_sizes[1] / 2;
    const int G = in_sizes[3] / RDK;
    const int* row = ei;
    const int* col = ei + E;

    float *dinv, *wsum, *stats, *pool, *cnt, *z, *z1, *z2;
    __half *x16, *h16, *agg16, *w1h, *w2h;
    int *degc, *csr, *ovf, *ovfcnt;
    cudaGetSymbolAddress((void**)&dinv,  g_dinv);
    cudaGetSymbolAddress((void**)&wsum,  g_wsum);
    cudaGetSymbolAddress((void**)&degc,  g_degc);
    cudaGetSymbolAddress((void**)&csr,   g_csr);
    cudaGetSymbolAddress((void**)&ovf,   g_ovf);
    cudaGetSymbolAddress((void**)&ovfcnt,g_ovfcnt);
    cudaGetSymbolAddress((void**)&x16,   g_x16);
    cudaGetSymbolAddress((void**)&h16,   g_h16);
    cudaGetSymbolAddress((void**)&agg16, g_agg16);
    cudaGetSymbolAddress((void**)&w1h,   g_w1h);
    cudaGetSymbolAddress((void**)&w2h,   g_w2h);
    cudaGetSymbolAddress((void**)&stats, g_stats);
    cudaGetSymbolAddress((void**)&pool,  g_pool);
    cudaGetSymbolAddress((void**)&cnt,   g_cnt);
    cudaGetSymbolAddress((void**)&z,     g_z);
    cudaGetSymbolAddress((void**)&z1,    g_z1);
    cudaGetSymbolAddress((void**)&z2,    g_z2);

    float* s_bn1  = stats;          // 2*H1
    float* s_bn2  = stats + 256;    // 2*HH
    float* s_mbn1 = stats + 768;    // 2*HH
    float* s_mbn2 = stats + 1280;   // 2*H1

    const float invN = 1.0f / (float)N;
    const float invG = 1.0f / (float)G;

    auto cdiv = [](long long a, long long b) { return (int)((a + b - 1) / b); };

    // --- setup, CSR build, dinv + cnt + prescale x ---
    {
        long long total = (long long)N + 1 + STATS_TOTAL + (long long)G * HH + G +
                          F_DIM * H1 / 4 + H1 * HH / 4;
        k_setup<<<cdiv(total, 256), 256>>>(degc, ovfcnt, stats, pool, cnt,
                                           W1, w1h, W2, w2h, N, G);
    }
    k_csr_build<<<cdiv(E, 256), 256>>>(row, col, degc, csr, ovf, ovfcnt, E);
    k_dinv_prescale<<<cdiv((long long)N * (F_DIM / 4), 256), 256>>>(
        degc, dinv, batch, cnt, x, x16, N);

    // --- layer 1 ---
    k_gather_h<F_DIM, false><<<cdiv((long long)N * 32, 256), 256>>>(
        csr, degc, dinv, x16, nullptr, nullptr, nullptr, invN, wsum, agg16, N);
    k_overflow_h<F_DIM, false><<<1, 256>>>(row, col, ovf, ovfcnt, dinv, x16,
                                           nullptr, nullptr, nullptr, invN, agg16);
    {
        dim3 grid(cdiv(N, 128), 1);
        k_gemm_h<false, 2><<<grid, 256>>>(agg16, w1h, b1, h16, dinv,
                                          nullptr, nullptr, s_bn1, N, F_DIM, H1);
    }

    // --- layer 2 ---
    k_gather_h<H1, true><<<cdiv((long long)N * 32, 256), 256>>>(
        csr, degc, dinv, h16, s_bn1, gm1, be1, invN, wsum, agg16, N);
    k_overflow_h<H1, true><<<1, 256>>>(row, col, ovf, ovfcnt, dinv, h16,
                                       s_bn1, gm1, be1, invN, agg16);
    {
        dim3 grid(cdiv(N, 128), HH / 128);
        k_gemm_h<true, 0><<<grid, 256>>>(agg16, w2h, b2, nullptr, nullptr,
                                         batch, pool, s_bn2, N, H1, HH);
    }

    // --- concat (mean + BN2 coef+apply inline) ---
    k_concat<<<cdiv((long long)G * ZD, 256), 256>>>(pool, cnt, s_bn2, gm2, be2, invN,
                                                    rdkit, z, G);

    // --- MLP head ---
    {
        dim3 grid(cdiv(G, 128), HH / 128);
        k_gemm128<<<grid, 256>>>(z, mW1, mb1, z1, s_mbn1, G, ZD, HH);
    }
    k_bn_apply<HH><<<cdiv((long long)G * HH, 256), 256>>>(z1, s_mbn1, mg1, mbe1, G);

    {
        dim3 grid(cdiv(G, 128), 1);
        k_gemm128<<<grid, 256>>>(z1, mW2, mb2, z2, s_mbn2, G, HH, H1);
    }
    k_final<<<cdiv((long long)G * 32, 256), 256>>>(z2, s_mbn2, mg2, mbe2, invG,
                                                   mW3, mb3, out, G);
}

// round 13
// speedup vs baseline: 1.0481x; 1.0481x over previous
#include <cuda_runtime.h>
#include <cuda_fp16.h>
#include <mma.h>

using namespace nvcuda;

// ---------------------------------------------------------------------------
// HybridGNN: 2x GCNConv(+ReLU+BN) -> global mean pool -> concat rdkit ->
//            MLP (Linear+ReLU+BN) x2 -> Linear -> [G]
// Rows prescaled by their own dinv =>
//   agg[n] = dn*(src'[n] + sum src'[r]); wsum[n] = dn*(dn + sum dinv[r])
// wsum computed in a decoupled pre-loop (keeps the feature loop lean).
// ---------------------------------------------------------------------------

namespace {
constexpr int F_DIM = 64;
constexpr int H1    = 128;
constexpr int HH    = 256;   // 2H
constexpr int RDK   = 200;
constexpr int ZD    = 456;   // 2H + R
constexpr int NMAX  = 100000;
constexpr int GMAX  = 4096;
constexpr int SLOTS = 96;
constexpr int OFCAP = 4096;
constexpr int STATS_TOTAL = 1536;
constexpr float EPS = 1e-5f;
}

__device__ float  g_dinv[NMAX];
__device__ float  g_wsum[NMAX];
__device__ int    g_degc[NMAX];
__device__ int    g_csr [(size_t)NMAX * SLOTS];
__device__ int    g_ovf [OFCAP];
__device__ int    g_ovfcnt;
__device__ __half g_x16 [(size_t)NMAX * F_DIM];   // prescaled: dinv[n]*x[n]
__device__ __half g_h16 [(size_t)NMAX * H1];      // prescaled: dinv[n]*h1[n]
__device__ __half g_agg16[(size_t)NMAX * H1];
__device__ __half g_w1h[F_DIM * H1];
__device__ __half g_w2h[H1 * HH];
__device__ float  g_stats[STATS_TOTAL];
__device__ float  g_pool[(size_t)GMAX * HH];
__device__ float  g_cnt [GMAX];
__device__ float  g_z   [(size_t)GMAX * ZD];
__device__ float  g_z1  [(size_t)GMAX * HH];
__device__ float  g_z2  [(size_t)GMAX * H1];

__device__ __forceinline__ void red4(float* p, float4 v) {
    asm volatile("red.global.add.v4.f32 [%0], {%1,%2,%3,%4};"
                 :: "l"(p), "f"(v.x), "f"(v.y), "f"(v.z), "f"(v.w)
                 : "memory");
}

__device__ __forceinline__ void f2h4(const float* in, __half* out, size_t i4) {
    float4 v = ((const float4*)in)[i4];
    __half2 a = __floats2half2_rn(v.x, v.y);
    __half2 b = __floats2half2_rn(v.z, v.w);
    uint2 packed;
    packed.x = *(unsigned int*)&a;
    packed.y = *(unsigned int*)&b;
    ((uint2*)out)[i4] = packed;
}

// ---------------------------------------------------------------------------
// Setup: zero degc/ovfcnt/stats/pool/cnt + fp16-convert W1, W2
// ---------------------------------------------------------------------------
__global__ void k_setup(int* degc, int* ovfcnt, float* stats, float* pool, float* cnt,
                        const float* W1, __half* w1h,
                        const float* W2, __half* w2h, int N, int G) {
    long long i = (long long)blockIdx.x * blockDim.x + threadIdx.x;
    long long o0 = N;
    long long o1 = o0 + 1;
    long long o2 = o1 + STATS_TOTAL;
    long long o3 = o2 + (long long)G * HH;
    long long o4 = o3 + G;
    long long o5 = o4 + F_DIM * H1 / 4;
    long long o6 = o5 + H1 * HH / 4;
    if (i < o0)      degc[i] = 0;
    else if (i < o1) *ovfcnt = 0;
    else if (i < o2) stats[i - o1] = 0.0f;
    else if (i < o3) pool[i - o2] = 0.0f;
    else if (i < o4) cnt[i - o3] = 0.0f;
    else if (i < o5) f2h4(W1, w1h, i - o4);
    else if (i < o6) f2h4(W2, w2h, i - o5);
}

// ---------------------------------------------------------------------------
// CSR build
// ---------------------------------------------------------------------------
__global__ void k_csr_build(const int* __restrict__ row, const int* __restrict__ col,
                            int* __restrict__ cursor, int* __restrict__ csr,
                            int* __restrict__ ovf, int* __restrict__ ovfcnt, int E) {
    int e = blockIdx.x * blockDim.x + threadIdx.x;
    if (e >= E) return;
    int c = col[e];
    int slot = atomicAdd(&cursor[c], 1);
    if (slot < SLOTS) {
        csr[(size_t)c * SLOTS + slot] = row[e];
    } else {
        int o = atomicAdd(ovfcnt, 1);
        if (o < OFCAP) ovf[o] = e;
    }
}

// dinv + per-graph counts + prescale x -> fp16
__global__ void k_dinv_prescale(const int* __restrict__ deg, float* __restrict__ dinv,
                                const int* __restrict__ batch, float* __restrict__ cnt,
                                const float* __restrict__ x, __half* __restrict__ x16,
                                int N) {
    long long t = (long long)blockIdx.x * blockDim.x + threadIdx.x;
    if (t >= (long long)N * (F_DIM / 4)) return;
    int n  = (int)(t >> 4);
    int f4 = (int)(t & 15);
    float dv = rsqrtf((float)deg[n] + 1.0f);
    if (f4 == 0) {
        dinv[n] = dv;
        atomicAdd(&cnt[batch[n]], 1.0f);
    }
    float4 v = ((const float4*)x)[t];
    __half2 a = __floats2half2_rn(v.x * dv, v.y * dv);
    __half2 b = __floats2half2_rn(v.z * dv, v.w * dv);
    uint2 packed;
    packed.x = *(unsigned int*)&a;
    packed.y = *(unsigned int*)&b;
    ((uint2*)x16)[t] = packed;
}

// ---------------------------------------------------------------------------
// Gather (warp per node), prescaled fp16 src, fp32 accum, fp16 out.
//   M==64 (layer 1, !AFFINE): out = dn*acc; wsum[n] from a decoupled pre-loop.
//   M==128 (layer 2, AFFINE): out = a(.)(dn*acc) + wsum[n]*b
// Hot loops: simple fully-unrolled bodies (ptxas pipelines best).
// ---------------------------------------------------------------------------
template <int M, bool AFFINE>
__global__ void k_gather_h(const int* __restrict__ csr, const int* __restrict__ deg,
                           const float* __restrict__ dinv, const __half* __restrict__ src,
                           const float* __restrict__ stats,
                           const float* __restrict__ gamma, const float* __restrict__ beta,
                           float invN, float* __restrict__ wsum_buf,
                           __half* __restrict__ out, int N) {
    __shared__ float sca[AFFINE ? M : 1];
    __shared__ float scb[AFFINE ? M : 1];
    if constexpr (AFFINE) {
        for (int f = threadIdx.x; f < M; f += blockDim.x) {
            float mu = stats[f] * invN;
            float var = stats[M + f] * invN - mu * mu;
            float a = gamma[f] * rsqrtf(var + EPS);
            sca[f] = a;
            scb[f] = beta[f] - a * mu;
        }
        __syncthreads();
    }

    int warp = (blockIdx.x * blockDim.x + threadIdx.x) >> 5;
    int lane = threadIdx.x & 31;
    if (warp >= N) return;
    const int n = warp;
    int d = deg[n];
    if (d > SLOTS) d = SLOTS;
    const float dn = dinv[n];
    const int* list = csr + (size_t)n * SLOTS;

    if constexpr (M == 128) {
        const float w = wsum_buf[n];
        uint2 raw = ((const uint2*)(src + (size_t)n * M))[lane];
        float2 f0 = __half22float2(*(__half2*)&raw.x);
        float2 f1 = __half22float2(*(__half2*)&raw.y);
        float4 acc = make_float4(f0.x, f0.y, f1.x, f1.y);
        for (int base = 0; base < d; base += 32) {
            int li = base + lane;
            int idx = (li < d) ? list[li] : 0;
#define GA_BODY(j)                                                             \
            {                                                                  \
                int r0 = __shfl_sync(0xffffffffu, idx, (j));                   \
                uint2 rv = ((const uint2*)(src + (size_t)r0 * M))[lane];       \
                float2 v0 = __half22float2(*(__half2*)&rv.x);                  \
                float2 v1 = __half22float2(*(__half2*)&rv.y);                  \
                acc.x += v0.x; acc.y += v0.y; acc.z += v1.x; acc.w += v1.y;    \
            }
            if (d - base >= 32) {
#pragma unroll
                for (int j = 0; j < 32; j++) GA_BODY(j)
            } else {
                int m = d - base;
                for (int j = 0; j < m; j++) GA_BODY(j)
            }
#undef GA_BODY
        }
        acc.x *= dn; acc.y *= dn; acc.z *= dn; acc.w *= dn;
        float4 a4 = ((const float4*)sca)[lane];
        float4 b4 = ((const float4*)scb)[lane];
        acc.x = a4.x * acc.x + w * b4.x;
        acc.y = a4.y * acc.y + w * b4.y;
        acc.z = a4.z * acc.z + w * b4.z;
        acc.w = a4.w * acc.w + w * b4.w;
        __half2 o0 = __floats2half2_rn(acc.x, acc.y);
        __half2 o1 = __floats2half2_rn(acc.z, acc.w);
        uint2 packed;
        packed.x = *(unsigned int*)&o0;
        packed.y = *(unsigned int*)&o1;
        ((uint2*)(out + (size_t)n * M))[lane] = packed;
    } else {  // M == 64, layer 1: wsum from decoupled pre-loop
        float dsum = 0.0f;
        for (int li = lane; li < d; li += 32)
            dsum += dinv[list[li]];
#pragma unroll
        for (int off = 16; off > 0; off >>= 1)
            dsum += __shfl_xor_sync(0xffffffffu, dsum, off);
        if (lane == 0) wsum_buf[n] = dn * (dn + dsum);

        unsigned int raw = ((const unsigned int*)(src + (size_t)n * M))[lane];
        float2 f0 = __half22float2(*(__half2*)&raw);
        float2 acc = make_float2(f0.x, f0.y);
        for (int base = 0; base < d; base += 32) {
            int li = base + lane;
            int idx = (li < d) ? list[li] : 0;
#define GB_BODY(j)                                                             \
            {                                                                  \
                int r0 = __shfl_sync(0xffffffffu, idx, (j));                   \
                unsigned int rv = ((const unsigned int*)(src + (size_t)r0 * M))[lane]; \
                float2 v0 = __half22float2(*(__half2*)&rv);                    \
                acc.x += v0.x; acc.y += v0.y;                                  \
            }
            if (d - base >= 32) {
#pragma unroll
                for (int j = 0; j < 32; j++) GB_BODY(j)
            } else {
                int m = d - base;
                for (int j = 0; j < m; j++) GB_BODY(j)
            }
#undef GB_BODY
        }
        acc.x *= dn; acc.y *= dn;
        __half2 o0 = __floats2half2_rn(acc.x, acc.y);
        ((unsigned int*)(out + (size_t)n * M))[lane] = *(unsigned int*)&o0;
    }
}

// Overflow fallback (expected count 0), prescaled algebra
template <int M, bool AFFINE>
__global__ void k_overflow_h(const int* __restrict__ row, const int* __restrict__ col,
                             const int* __restrict__ ovf, const int* __restrict__ ovfcnt,
                             const float* __restrict__ dinv,
                             const __half* __restrict__ src,
                             const float* __restrict__ stats,
                             const float* __restrict__ gamma, const float* __restrict__ beta,
                             float invN, __half* __restrict__ dst) {
    __shared__ float sca[AFFINE ? M : 1];
    __shared__ float scb[AFFINE ? M : 1];
    if constexpr (AFFINE) {
        for (int f = threadIdx.x; f < M; f += blockDim.x) {
            float mu = stats[f] * invN;
            float var = stats[M + f] * invN - mu * mu;
            float a = gamma[f] * rsqrtf(var + EPS);
            sca[f] = a;
            scb[f] = beta[f] - a * mu;
        }
        __syncthreads();
    }
    int cnt = *ovfcnt;
    if (cnt > OFCAP) cnt = OFCAP;
    for (int i = threadIdx.x; i < cnt * (M / 4); i += blockDim.x) {
        int e = ovf[i / (M / 4)];
        int l = i % (M / 4);
        int r = row[e], c = col[e];
        float dc = dinv[c];
        uint2 raw = ((const uint2*)(src + (size_t)r * M))[l];
        float2 f0 = __half22float2(*(__half2*)&raw.x);
        float2 f1 = __half22float2(*(__half2*)&raw.y);
        float4 v = make_float4(f0.x * dc, f0.y * dc, f1.x * dc, f1.y * dc);
        if constexpr (AFFINE) {
            float nrm = dc * dinv[r];
            float4 a4 = ((const float4*)sca)[l];
            float4 b4 = ((const float4*)scb)[l];
            v.x = a4.x * v.x + nrm * b4.x; v.y = a4.y * v.y + nrm * b4.y;
            v.z = a4.z * v.z + nrm * b4.z; v.w = a4.w * v.w + nrm * b4.w;
        }
        __half2* p = (__half2*)(dst + (size_t)c * M + l * 4);
        atomicAdd(p,     __floats2half2_rn(v.x, v.y));
        atomicAdd(p + 1, __floats2half2_rn(v.z, v.w));
    }
}

// ---------------------------------------------------------------------------
// fp16 HMMA GEMM: relu(A@B + bias), fused stats, optional POOL,
// STORE_MODE 0=none / 2=fp16 (row-scaled by rowscale[] if given).
// ---------------------------------------------------------------------------
template <bool POOL, int STORE_MODE>
__launch_bounds__(256)
__global__ void k_gemm_h(const __half* __restrict__ A, const __half* __restrict__ B,
                         const float* __restrict__ bias,
                         __half* __restrict__ C16, const float* __restrict__ rowscale,
                         const int* __restrict__ batch, float* __restrict__ pool,
                         float* __restrict__ stats,
                         int N, int K, int M) {
    constexpr int LDA = 32;
    constexpr int LDB = 144;
    __shared__ __half Ah[128 * LDA];
    __shared__ __half Bh[16 * LDB];
    __shared__ float  staging[64 * 128];

    const int tx   = threadIdx.x;
    const int warp = tx >> 5;
    const int wr   = warp >> 2;
    const int wc   = warp & 3;
    const int trow = tx >> 4;
    const int tcol = tx & 15;
    const int row0 = blockIdx.x * 128;
    const int colT = blockIdx.y * 128;
    const int c0   = colT + tcol * 8;

    wmma::fragment<wmma::accumulator, 16, 16, 16, float> acc[4][2];
#pragma unroll
    for (int m = 0; m < 4; m++)
#pragma unroll
        for (int n = 0; n < 2; n++) wmma::fill_fragment(acc[m][n], 0.0f);

    for (int k0 = 0; k0 < K; k0 += 16) {
        {
            int r  = tx >> 1;
            int h8 = (tx & 1) * 8;
            uint4 v = make_uint4(0, 0, 0, 0);
            int grow = row0 + r;
            if (grow < N) v = *(const uint4*)&A[(size_t)grow * K + k0 + h8];
            *(uint4*)&Ah[r * LDA + h8] = v;
        }
        {
            int kk = tx >> 4;
            int c8 = (tx & 15) * 8;
            uint4 v = *(const uint4*)&B[(size_t)(k0 + kk) * M + colT + c8];
            *(uint4*)&Bh[kk * LDB + c8] = v;
        }
        __syncthreads();

        wmma::fragment<wmma::matrix_b, 16, 16, 16, __half, wmma::row_major> bf[2];
#pragma unroll
        for (int n = 0; n < 2; n++)
            wmma::load_matrix_sync(bf[n], &Bh[wc * 32 + n * 16], LDB);
#pragma unroll
        for (int m = 0; m < 4; m++) {
            wmma::fragment<wmma::matrix_a, 16, 16, 16, __half, wmma::row_major> af;
            wmma::load_matrix_sync(af, &Ah[(wr * 64 + m * 16) * LDA], LDA);
#pragma unroll
            for (int n = 0; n < 2; n++)
                wmma::mma_sync(acc[m][n], af, bf[n], acc[m][n]);
        }
        __syncthreads();
    }

    float bv[8];
    *(float4*)&bv[0] = *(const float4*)&bias[c0];
    *(float4*)&bv[4] = *(const float4*)&bias[c0 + 4];

    float s_part[8], q_part[8];
#pragma unroll
    for (int c = 0; c < 8; c++) { s_part[c] = 0.f; q_part[c] = 0.f; }

#pragma unroll
    for (int half = 0; half < 2; half++) {
#pragma unroll
        for (int mi = 0; mi < 2; mi++)
#pragma unroll
            for (int n = 0; n < 2; n++)
                wmma::store_matrix_sync(&staging[(wr * 32 + mi * 16) * 128 + wc * 32 + n * 16],
                                        acc[2 * half + mi][n], 128, wmma::mem_row_major);
        __syncthreads();

#pragma unroll
        for (int k = 0; k < 4; k++) {
            int r_st = trow * 4 + k;
            int grow = row0 + (r_st >> 5) * 64 + (half * 2 + ((r_st >> 4) & 1)) * 16 + (r_st & 15);
            if (grow < N) {
                float v[8];
                *(float4*)&v[0] = *(float4*)&staging[r_st * 128 + tcol * 8];
                *(float4*)&v[4] = *(float4*)&staging[r_st * 128 + tcol * 8 + 4];
#pragma unroll
                for (int c = 0; c < 8; c++) {
                    v[c] = fmaxf(v[c] + bv[c], 0.0f);
                    s_part[c] += v[c];
                    q_part[c] += v[c] * v[c];
                }
                if constexpr (STORE_MODE == 2) {
                    float rs = rowscale ? rowscale[grow] : 1.0f;
                    __half hv[8];
#pragma unroll
                    for (int c = 0; c < 8; c++) hv[c] = __float2half_rn(v[c] * rs);
                    *(uint4*)&C16[(size_t)grow * M + c0] = *(uint4*)hv;
                }
                if constexpr (POOL) {
                    int g = batch[grow];
                    red4(pool + (size_t)g * M + c0,     *(float4*)&v[0]);
                    red4(pool + (size_t)g * M + c0 + 4, *(float4*)&v[4]);
                }
            }
        }
        __syncthreads();
    }

    float* Rsum = staging;
    float* Rsq  = staging + 16 * 128;
    *(float4*)&Rsum[trow * 128 + tcol * 8]     = *(float4*)&s_part[0];
    *(float4*)&Rsum[trow * 128 + tcol * 8 + 4] = *(float4*)&s_part[4];
    *(float4*)&Rsq [trow * 128 + tcol * 8]     = *(float4*)&q_part[0];
    *(float4*)&Rsq [trow * 128 + tcol * 8 + 4] = *(float4*)&q_part[4];
    __syncthreads();
#pragma unroll
    for (int st = 8; st >= 1; st >>= 1) {
        if (trow < st) {
#pragma unroll
            for (int c = 0; c < 8; c++) {
                Rsum[trow * 128 + tcol * 8 + c] += Rsum[(trow + st) * 128 + tcol * 8 + c];
                Rsq [trow * 128 + tcol * 8 + c] += Rsq [(trow + st) * 128 + tcol * 8 + c];
            }
        }
        __syncthreads();
    }
    if (trow == 0) {
#pragma unroll
        for (int c = 0; c < 8; c++) {
            atomicAdd(&stats[c0 + c],     Rsum[tcol * 8 + c]);
            atomicAdd(&stats[M + c0 + c], Rsq [tcol * 8 + c]);
        }
    }
}

// ---------------------------------------------------------------------------
// fp32 SGEMM (MLP head): stats fused, fp32 C
// ---------------------------------------------------------------------------
__launch_bounds__(256, 2)
__global__ void k_gemm128(const float* __restrict__ A, const float* __restrict__ B,
                          const float* __restrict__ bias, float* __restrict__ C,
                          float* __restrict__ stats,
                          int N, int K, int M) {
    constexpr int BM = 128, BN = 128, KT = 16;
    __shared__ float As[KT][BM];
    __shared__ float Bs[KT][BN];

    const int row0 = blockIdx.x * BM;
    const int colT = blockIdx.y * BN;
    const int tx   = threadIdx.x;
    const int tcol = tx & 15;
    const int trow = tx >> 4;
    const int c0   = colT + tcol * 8;
    const int r0   = row0 + trow * 8;

    float acc[8][8];
#pragma unroll
    for (int r = 0; r < 8; r++)
#pragma unroll
        for (int c = 0; c < 8; c++) acc[r][c] = 0.0f;

    for (int k0 = 0; k0 < K; k0 += KT) {
#pragma unroll
        for (int i = 0; i < 2; i++) {
            int idx = tx + i * 256;
            int kk  = idx >> 5;
            int cq  = idx & 31;
            int k   = k0 + kk;
            float4 v = make_float4(0.f, 0.f, 0.f, 0.f);
            if (k < K) v = *(const float4*)&B[(size_t)k * M + colT + cq * 4];
            *(float4*)&Bs[kk][cq * 4] = v;
        }
#pragma unroll
        for (int i = 0; i < 2; i++) {
            int idx = tx + i * 256;
            int r   = idx >> 2;
            int kq  = idx & 3;
            int row = row0 + r;
            int k   = k0 + kq * 4;
            float4 v = make_float4(0.f, 0.f, 0.f, 0.f);
            if (row < N) {
                if (k + 3 < K) {
                    v = *(const float4*)&A[(size_t)row * K + k];
                } else {
                    float t0 = (k + 0 < K) ? A[(size_t)row * K + k + 0] : 0.f;
                    float t1 = (k + 1 < K) ? A[(size_t)row * K + k + 1] : 0.f;
                    float t2 = (k + 2 < K) ? A[(size_t)row * K + k + 2] : 0.f;
                    float t3 = (k + 3 < K) ? A[(size_t)row * K + k + 3] : 0.f;
                    v = make_float4(t0, t1, t2, t3);
                }
            }
            As[kq * 4 + 0][r] = v.x;
            As[kq * 4 + 1][r] = v.y;
            As[kq * 4 + 2][r] = v.z;
            As[kq * 4 + 3][r] = v.w;
        }
        __syncthreads();

#pragma unroll
        for (int kk = 0; kk < KT; kk++) {
            float a[8], b[8];
            *(float4*)&a[0] = *(const float4*)&As[kk][trow * 8];
            *(float4*)&a[4] = *(const float4*)&As[kk][trow * 8 + 4];
            *(float4*)&b[0] = *(const float4*)&Bs[kk][tcol * 8];
            *(float4*)&b[4] = *(const float4*)&Bs[kk][tcol * 8 + 4];
#pragma unroll
            for (int r = 0; r < 8; r++)
#pragma unroll
                for (int c = 0; c < 8; c++)
                    acc[r][c] += a[r] * b[c];
        }
        __syncthreads();
    }

    float bv[8];
    *(float4*)&bv[0] = *(const float4*)&bias[c0];
    *(float4*)&bv[4] = *(const float4*)&bias[c0 + 4];

    float s_part[8], q_part[8];
#pragma unroll
    for (int c = 0; c < 8; c++) { s_part[c] = 0.f; q_part[c] = 0.f; }

#pragma unroll
    for (int r = 0; r < 8; r++) {
        int row = r0 + r;
        if (row < N) {
#pragma unroll
            for (int c = 0; c < 8; c++) {
                acc[r][c] = fmaxf(acc[r][c] + bv[c], 0.0f);
                s_part[c] += acc[r][c];
                q_part[c] += acc[r][c] * acc[r][c];
            }
            *(float4*)&C[(size_t)row * M + c0]     = *(float4*)&acc[r][0];
            *(float4*)&C[(size_t)row * M + c0 + 4] = *(float4*)&acc[r][4];
        }
    }

    *(float4*)&As[trow][tcol * 8]     = *(float4*)&s_part[0];
    *(float4*)&As[trow][tcol * 8 + 4] = *(float4*)&s_part[4];
    *(float4*)&Bs[trow][tcol * 8]     = *(float4*)&q_part[0];
    *(float4*)&Bs[trow][tcol * 8 + 4] = *(float4*)&q_part[4];
    __syncthreads();
#pragma unroll
    for (int st = 8; st >= 1; st >>= 1) {
        if (trow < st) {
#pragma unroll
            for (int c = 0; c < 8; c++) {
                As[trow][tcol * 8 + c] += As[trow + st][tcol * 8 + c];
                Bs[trow][tcol * 8 + c] += Bs[trow + st][tcol * 8 + c];
            }
        }
        __syncthreads();
    }
    if (trow == 0) {
#pragma unroll
        for (int c = 0; c < 8; c++) {
            atomicAdd(&stats[c0 + c],     As[0][tcol * 8 + c]);
            atomicAdd(&stats[M + c0 + c], Bs[0][tcol * 8 + c]);
        }
    }
}

// ---------------------------------------------------------------------------
// BN apply (mBN1 on z1)
// ---------------------------------------------------------------------------
template <int M>
__global__ void k_bn_apply(float* __restrict__ h, const float* __restrict__ stats,
                           const float* __restrict__ gamma, const float* __restrict__ beta,
                           int N) {
    size_t i = (size_t)blockIdx.x * blockDim.x + threadIdx.x;
    if (i >= (size_t)N * M) return;
    int f = (int)(i % M);
    float inv_n = 1.0f / (float)N;
    float mu = stats[f] * inv_n;
    float var = stats[M + f] * inv_n - mu * mu;
    float sc = gamma[f] * rsqrtf(var + EPS);
    h[i] = (h[i] - mu) * sc + beta[f];
}

// ---------------------------------------------------------------------------
// Concat: mean + BN2-apply (coef inline) + rdkit
// ---------------------------------------------------------------------------
__global__ void k_concat(const float* __restrict__ pool, const float* __restrict__ cnt,
                         const float* __restrict__ stats,
                         const float* __restrict__ gamma, const float* __restrict__ beta,
                         float invN,
                         const float* __restrict__ rdkit, float* __restrict__ z, int G) {
    int t = blockIdx.x * blockDim.x + threadIdx.x;
    if (t >= G * ZD) return;
    int g = t / ZD, f = t % ZD;
    float out;
    if (f < HH) {
        float mu = stats[f] * invN;
        float var = stats[HH + f] * invN - mu * mu;
        float a = gamma[f] * rsqrtf(var + EPS);
        float b = beta[f] - a * mu;
        float mean = pool[(size_t)g * HH + f] / fmaxf(cnt[g], 1.0f);
        out = a * mean + b;
    } else {
        out = rdkit[(size_t)g * RDK + (f - HH)];
    }
    z[t] = out;
}

// ---------------------------------------------------------------------------
// Final projection with mBN2-apply folded in
// ---------------------------------------------------------------------------
__global__ void k_final(const float* __restrict__ z2, const float* __restrict__ stats,
                        const float* __restrict__ gamma, const float* __restrict__ beta,
                        float invG,
                        const float* __restrict__ w, const float* __restrict__ b,
                        float* __restrict__ out, int G) {
    int warp = (blockIdx.x * blockDim.x + threadIdx.x) >> 5;
    int lane = threadIdx.x & 31;
    if (warp >= G) return;
    const float* zr = z2 + (size_t)warp * H1;
    float s = 0.0f;
#pragma unroll
    for (int q = 0; q < 4; q++) {
        int f = lane + q * 32;
        float mu = stats[f] * invG;
        float var = stats[H1 + f] * invG - mu * mu;
        float a = gamma[f] * rsqrtf(var + EPS);
        float bb = beta[f] - a * mu;
        s += w[f] * (a * zr[f] + bb);
    }
#pragma unroll
    for (int off = 16; off > 0; off >>= 1)
        s += __shfl_down_sync(0xffffffffu, s, off);
    if (lane == 0) out[warp] = s + b[0];
}

// ---------------------------------------------------------------------------
// Launch
// ---------------------------------------------------------------------------
extern "C" void kernel_launch(void* const* d_in, const int* in_sizes, int n_in,
                              void* d_out, int out_size) {
    const float* x      = (const float*)d_in[0];
    const int*   ei     = (const int*)d_in[1];
    const int*   batch  = (const int*)d_in[2];
    const float* rdkit  = (const float*)d_in[3];
    const float* W1  = (const float*)d_in[4];
    const float* b1  = (const float*)d_in[5];
    const float* gm1 = (const float*)d_in[6];
    const float* be1 = (const float*)d_in[7];
    const float* W2  = (const float*)d_in[8];
    const float* b2  = (const float*)d_in[9];
    const float* gm2 = (const float*)d_in[10];
    const float* be2 = (const float*)d_in[11];
    const float* mW1 = (const float*)d_in[12];
    const float* mb1 = (const float*)d_in[13];
    const float* mg1 = (const float*)d_in[14];
    const float* mbe1= (const float*)d_in[15];
    const float* mW2 = (const float*)d_in[16];
    const float* mb2 = (const float*)d_in[17];
    const float* mg2 = (const float*)d_in[18];
    const float* mbe2= (const float*)d_in[19];
    const float* mW3 = (const float*)d_in[20];
    const float* mb3 = (const float*)d_in[21];
    float* out = (float*)d_out;

    const int N = in_sizes[2];
    const int E = in_sizes[1] / 2;
    const int G = in_sizes[3] / RDK;
    const int* row = ei;
    const int* col = ei + E;

    float *dinv, *wsum, *stats, *pool, *cnt, *z, *z1, *z2;
    __half *x16, *h16, *agg16, *w1h, *w2h;
    int *degc, *csr, *ovf, *ovfcnt;
    cudaGetSymbolAddress((void**)&dinv,  g_dinv);
    cudaGetSymbolAddress((void**)&wsum,  g_wsum);
    cudaGetSymbolAddress((void**)&degc,  g_degc);
    cudaGetSymbolAddress((void**)&csr,   g_csr);
    cudaGetSymbolAddress((void**)&ovf,   g_ovf);
    cudaGetSymbolAddress((void**)&ovfcnt,g_ovfcnt);
    cudaGetSymbolAddress((void**)&x16,   g_x16);
    cudaGetSymbolAddress((void**)&h16,   g_h16);
    cudaGetSymbolAddress((void**)&agg16, g_agg16);
    cudaGetSymbolAddress((void**)&w1h,   g_w1h);
    cudaGetSymbolAddress((void**)&w2h,   g_w2h);
    cudaGetSymbolAddress((void**)&stats, g_stats);
    cudaGetSymbolAddress((void**)&pool,  g_pool);
    cudaGetSymbolAddress((void**)&cnt,   g_cnt);
    cudaGetSymbolAddress((void**)&z,     g_z);
    cudaGetSymbolAddress((void**)&z1,    g_z1);
    cudaGetSymbolAddress((void**)&z2,    g_z2);

    float* s_bn1  = stats;          // 2*H1
    float* s_bn2  = stats + 256;    // 2*HH
    float* s_mbn1 = stats + 768;    // 2*HH
    float* s_mbn2 = stats + 1280;   // 2*H1

    const float invN = 1.0f / (float)N;
    const float invG = 1.0f / (float)G;

    auto cdiv = [](long long a, long long b) { return (int)((a + b - 1) / b); };

    // --- setup, CSR build, dinv + cnt + prescale x ---
    {
        long long total = (long long)N + 1 + STATS_TOTAL + (long long)G * HH + G +
                          F_DIM * H1 / 4 + H1 * HH / 4;
        k_setup<<<cdiv(total, 256), 256>>>(degc, ovfcnt, stats, pool, cnt,
                                           W1, w1h, W2, w2h, N, G);
    }
    k_csr_build<<<cdiv(E, 256), 256>>>(row, col, degc, csr, ovf, ovfcnt, E);
    k_dinv_prescale<<<cdiv((long long)N * (F_DIM / 4), 256), 256>>>(
        degc, dinv, batch, cnt, x, x16, N);

    // --- layer 1 ---
    k_gather_h<F_DIM, false><<<cdiv((long long)N * 32, 256), 256>>>(
        csr, degc, dinv, x16, nullptr, nullptr, nullptr, invN, wsum, agg16, N);
    k_overflow_h<F_DIM, false><<<1, 256>>>(row, col, ovf, ovfcnt, dinv, x16,
                                           nullptr, nullptr, nullptr, invN, agg16);
    {
        dim3 grid(cdiv(N, 128), 1);
        k_gemm_h<false, 2><<<grid, 256>>>(agg16, w1h, b1, h16, dinv,
                                          nullptr, nullptr, s_bn1, N, F_DIM, H1);
    }

    // --- layer 2 ---
    k_gather_h<H1, true><<<cdiv((long long)N * 32, 256), 256>>>(
        csr, degc, dinv, h16, s_bn1, gm1, be1, invN, wsum, agg16, N);
    k_overflow_h<H1, true><<<1, 256>>>(row, col, ovf, ovfcnt, dinv, h16,
                                       s_bn1, gm1, be1, invN, agg16);
    {
        dim3 grid(cdiv(N, 128), HH / 128);
        k_gemm_h<true, 0><<<grid, 256>>>(agg16, w2h, b2, nullptr, nullptr,
                                         batch, pool, s_bn2, N, H1, HH);
    }

    // --- concat (mean + BN2 coef+apply inline) ---
    k_concat<<<cdiv((long long)G * ZD, 256), 256>>>(pool, cnt, s_bn2, gm2, be2, invN,
                                                    rdkit, z, G);

    // --- MLP head ---
    {
        dim3 grid(cdiv(G, 128), HH / 128);
        k_gemm128<<<grid, 256>>>(z, mW1, mb1, z1, s_mbn1, G, ZD, HH);
    }
    k_bn_apply<HH><<<cdiv((long long)G * HH, 256), 256>>>(z1, s_mbn1, mg1, mbe1, G);

    {
        dim3 grid(cdiv(G, 128), 1);
        k_gemm128<<<grid, 256>>>(z1, mW2, mb2, z2, s_mbn2, G, HH, H1);
    }
    k_final<<<cdiv((long long)G * 32, 256), 256>>>(z2, s_mbn2, mg2, mbe2, invG,
                                                   mW3, mb3, out, G);
}